// round 1
// baseline (speedup 1.0000x reference)
#include <cuda_runtime.h>
#include <math.h>

// RBFSolver: out[0,f,t] = sum_k w_k / (1 + 4pi^2 ex^2)
//            out[1,f,t] = -2pi sum_k w_k ex / (1 + 4pi^2 ex^2)
// with ex = exp(log f + log_t + y_k), y = linspace(-50,50,500),
// w_k = exp(-y_k^2) * dy.
//
// Key facts exploited:
//  * ex = exp(s) * exp(y_k): one exp per (f,t), table for exp(y_k).
//  * w_k = exp(-y_k^2)*dy < 2e-22 outside |y| <= 6.92 (k in [215,284]):
//    truncate K 500 -> 70 with relative error < 1e-17 (tol is 1e-3).
//  * With exF = 2pi*ex: denom = fma(exF,exF,1) and
//    sum w*exF/denom == -a_im exactly (the 2pi folds in).

#define NY_K0   215
#define NY_KNUM 70
#define F_DIM   512
#define T_DIM   256

__global__ __launch_bounds__(T_DIM, 8)
void rbf_solver_kernel(const float* __restrict__ f_vec,
                       const float* __restrict__ log_t_vec,
                       float* __restrict__ out)
{
    __shared__ float2 ew[NY_KNUM];   // (exp(y_k)*2pi folded later, w_k)

    const float dy = 100.0f / 499.0f;

    // Build the quadrature table once per block (70 entries, 256 threads).
    if (threadIdx.x < NY_KNUM) {
        float y = fmaf((float)(NY_K0 + (int)threadIdx.x), dy, -50.0f);
        float E = __expf(y);
        float w = __expf(-y * y) * dy;
        ew[threadIdx.x] = make_float2(E, w);
    }
    __syncthreads();

    const int f = blockIdx.x;     // 0..511
    const int t = threadIdx.x;    // 0..255

    const float s  = __logf(f_vec[f]) + log_t_vec[t];
    const float two_pi = 6.283185307179586f;          // sqrt(4*pi^2)
    const float esc = __expf(s) * two_pi;             // 2pi * exp(s)

    float re = 0.0f;
    float im = 0.0f;   // accumulates 2pi * sum w*ex/denom  == -a_im

    #pragma unroll 7
    for (int i = 0; i < NY_KNUM; ++i) {
        float2 v   = ew[i];                  // broadcast LDS.64
        float exF  = esc * v.x;              // 2pi * ex
        float d    = fmaf(exF, exF, 1.0f);   // 1 + 4pi^2 ex^2
        float tw   = __fdividef(v.y, d);     // w * rcp.approx(d)
        re        += tw;
        im         = fmaf(tw, exF, im);
    }

    const int idx = f * T_DIM + t;
    out[idx]                 = re;     // a_re
    out[F_DIM * T_DIM + idx] = -im;    // a_im
}

extern "C" void kernel_launch(void* const* d_in, const int* in_sizes, int n_in,
                              void* d_out, int out_size)
{
    const float* f_vec     = (const float*)d_in[0];   // (512,)
    const float* log_t_vec = (const float*)d_in[1];   // (256,)
    float* out             = (float*)d_out;           // (2, 512, 256)

    (void)in_sizes; (void)n_in; (void)out_size;

    rbf_solver_kernel<<<F_DIM, T_DIM>>>(f_vec, log_t_vec, out);
}

// round 2
// speedup vs baseline: 1.3092x; 1.3092x over previous
#include <cuda_runtime.h>
#include <math.h>

// RBFSolver: out[0,f,t] = sum_k w_k / (1 + 4pi^2 ex^2)
//            out[1,f,t] = -2pi sum_k w_k ex / (1 + 4pi^2 ex^2)
// ex = exp(log f + log t + y_k), y = linspace(-50,50,500), w_k = exp(-y_k^2)*dy.
//
// Optimizations:
//  * ex = exp(s)*exp(y_k): one exp per (f,t); 44-entry table for exp(y_k).
//  * Gaussian weights are negligible outside |y|<=4.5 (k=227..270):
//    K 500 -> 44, truncation error < 1e-5 relative (tolerance 1e-3).
//  * exF = 2pi*ex folds the final 2pi into the accumulation exactly.
//  * Packed f32x2 FMA-pipe math (sm_103a): 2 k-values per MUL/FMA/ADD,
//    halving FMA-pipe issue pressure. MUFU.RCP stays scalar (no f32x2 MUFU).

#define NY_K0   227
#define NY_PAIR 22      // 44 points, 22 packed pairs
#define F_DIM   512
#define T_DIM   256

typedef unsigned long long u64;

#define MUL2(o,a,b)   asm("mul.rn.f32x2 %0, %1, %2;"     : "=l"(o) : "l"(a), "l"(b))
#define ADD2(o,a,b)   asm("add.rn.f32x2 %0, %1, %2;"     : "=l"(o) : "l"(a), "l"(b))
#define FMA2(o,a,b,c) asm("fma.rn.f32x2 %0, %1, %2, %3;" : "=l"(o) : "l"(a), "l"(b), "l"(c))
#define PACK2(o,lo,hi)   asm("mov.b64 %0, {%1, %2};" : "=l"(o) : "f"(lo), "f"(hi))
#define UNPACK2(lo,hi,i) asm("mov.b64 {%0, %1}, %2;" : "=f"(lo), "=f"(hi) : "l"(i))
#define RCPA(o,a)     asm("rcp.approx.ftz.f32 %0, %1;" : "=f"(o) : "f"(a))

__global__ __launch_bounds__(T_DIM, 8)
void rbf_solver_kernel(const float* __restrict__ f_vec,
                       const float* __restrict__ log_t_vec,
                       float* __restrict__ out)
{
    // (E_2i, E_2i+1, w_2i, w_2i+1) — float4 so (x,y) and (z,w) land in
    // aligned register pairs usable directly as f32x2 operands.
    __shared__ float4 tbl[NY_PAIR];

    const float dy = 100.0f / 499.0f;

    if (threadIdx.x < NY_PAIR) {
        int k = NY_K0 + 2 * (int)threadIdx.x;
        float y0 = fmaf((float)k, dy, -50.0f);
        float y1 = y0 + dy;
        tbl[threadIdx.x] = make_float4(__expf(y0), __expf(y1),
                                       __expf(-y0 * y0) * dy,
                                       __expf(-y1 * y1) * dy);
    }
    __syncthreads();

    const int f = blockIdx.x;     // 0..511
    const int t = threadIdx.x;    // 0..255

    const float s   = __logf(f_vec[f]) + log_t_vec[t];
    const float esc = __expf(s) * 6.283185307179586f;   // 2pi * exp(s)

    u64 esc2, one2, re2, im2;
    PACK2(esc2, esc, esc);
    {
        float one = 1.0f, zero = 0.0f;
        PACK2(one2, one, one);
        PACK2(re2, zero, zero);
        PACK2(im2, zero, zero);
    }

    #pragma unroll
    for (int i = 0; i < NY_PAIR; ++i) {
        float4 v = tbl[i];                  // LDS.128 broadcast
        u64 E2, w2;
        PACK2(E2, v.x, v.y);
        PACK2(w2, v.z, v.w);

        u64 exF2;  MUL2(exF2, esc2, E2);            // 2pi*ex (x2)
        u64 d2;    FMA2(d2, exF2, exF2, one2);      // 1 + (2pi ex)^2 (x2)

        float dlo, dhi;  UNPACK2(dlo, dhi, d2);
        float rlo, rhi;
        RCPA(rlo, dlo);                             // MUFU.RCP
        RCPA(rhi, dhi);                             // MUFU.RCP
        u64 r2;    PACK2(r2, rlo, rhi);

        u64 tw2;   MUL2(tw2, w2, r2);               // w / denom (x2)
        ADD2(re2, re2, tw2);
        FMA2(im2, tw2, exF2, im2);                  // accumulates -a_im
    }

    float re_lo, re_hi, im_lo, im_hi;
    UNPACK2(re_lo, re_hi, re2);
    UNPACK2(im_lo, im_hi, im2);

    const int idx = f * T_DIM + t;
    out[idx]                 = re_lo + re_hi;       // a_re
    out[F_DIM * T_DIM + idx] = -(im_lo + im_hi);    // a_im
}

extern "C" void kernel_launch(void* const* d_in, const int* in_sizes, int n_in,
                              void* d_out, int out_size)
{
    const float* f_vec     = (const float*)d_in[0];   // (512,)
    const float* log_t_vec = (const float*)d_in[1];   // (256,)
    float* out             = (float*)d_out;           // (2, 512, 256)

    (void)in_sizes; (void)n_in; (void)out_size;

    rbf_solver_kernel<<<F_DIM, T_DIM>>>(f_vec, log_t_vec, out);
}